// round 17
// baseline (speedup 1.0000x reference)
#include <cuda_runtime.h>
#include <cstdint>

#define DM 2048
static __device__ float g_q [128*2048];
static __device__ float g_kn[128*2048];
static __device__ float g_vn[128*2048];
static __device__ float g_ao[128*2048];
static __device__ float g_part[8*128*2048];     // out-proj split-K partials (8 slices)
static __device__ float g_pqkv[9*128*2048];     // QKV split-K partials [sel*3+slice]
static __device__ int   g_cnt0[96];             // gemm0 groups: sel*32 + n0block
static __device__ int   g_cnt1[32];             // gemm1 groups: n0block

__device__ __forceinline__ uint32_t f2t(float x){
    uint32_t r; asm("cvt.rna.tf32.f32 %0,%1;":"=r"(r):"f"(x)); return r;
}
__device__ __forceinline__ float tf(float x){ return __uint_as_float(f2t(x)); }
__device__ __forceinline__ float ex2(float x){
    float r; asm("ex2.approx.ftz.f32 %0,%1;":"=f"(r):"f"(x)); return r;
}
__device__ __forceinline__ void mma8(float* c,uint32_t a0,uint32_t a1,uint32_t a2,uint32_t a3,
                                     uint32_t b0,uint32_t b1){
    asm volatile("mma.sync.aligned.m16n8k8.row.col.f32.tf32.tf32.f32 "
        "{%0,%1,%2,%3},{%4,%5,%6,%7},{%8,%9},{%0,%1,%2,%3};"
        :"+f"(c[0]),"+f"(c[1]),"+f"(c[2]),"+f"(c[3])
        :"r"(a0),"r"(a1),"r"(a2),"r"(a3),"r"(b0),"r"(b1));
}
__device__ __forceinline__ void cpa16(float* s, const float* g){
    uint32_t sa=(uint32_t)__cvta_generic_to_shared(s);
    asm volatile("cp.async.cg.shared.global [%0],[%1],16;" :: "r"(sa),"l"(g));
}
__device__ __forceinline__ void cpcommit(){ asm volatile("cp.async.commit_group;"); }
__device__ __forceinline__ void cpwait0(){ asm volatile("cp.async.wait_group 0;"); }
__device__ __forceinline__ void cpwait1(){ asm volatile("cp.async.wait_group 1;"); }

// ======================= GEMM with fused last-CTA reduce ==================
// 512 threads, 16 warps (8M x 2N), warp tile 16x32, KC32 2-stage cp.async.
// MODE0: x @ {Wq,Wk,Wv}, sel=blockIdx.y, slice=blockIdx.z (22/21/21 chunks)
//        -> partials; LAST CTA of each (sel,n0) group reduces+bias+scatters.
// MODE1: g_ao @ Wo, slice=blockIdx.y (8x8 chunks) -> partials; LAST CTA of
//        each n0 group reduces+bias -> d_out.
#define GEMM_SMEM ((2*128*36 + 2*32*72)*4)

template<int MODE>
__global__ __launch_bounds__(512) void gemm_k(const float* __restrict__ A,
    const float* __restrict__ W0,const float* __restrict__ W1,const float* __restrict__ W2,
    const float* __restrict__ B0,const float* __restrict__ B1,const float* __restrict__ B2,
    float* __restrict__ O)
{
    extern __shared__ float sm[];
    float* Xs = sm;
    float* Ws = sm + 2*4608;
    __shared__ int lastFlag;
    int tid=threadIdx.x, lane=tid&31, warp=tid>>5, tg=lane&3, gid=lane>>2;
    int sel = MODE? 0 : blockIdx.y;
    const float* W  = sel==0?W0: sel==1?W1:W2;
    const float* Bi = sel==0?B0: sel==1?B1:B2;
    const float* Ap = MODE? g_ao : A;
    int kcb, kcn;
    float* Out;
    if(MODE){
        int sl = blockIdx.y;
        kcb = sl*8; kcn = 8;
        Out = g_part + sl*262144;
    }else{
        int sl = blockIdx.z;
        kcb = (sl==0)?0:((sl==1)?22:43);
        kcn = (sl==0)?22:21;
        Out = g_pqkv + (sel*3+sl)*262144;
    }
    int n0 = blockIdx.x*64;
    int m0 = (warp&7)*16, nb = (warp>>3)*32;
    float acc[4][4];
    #pragma unroll
    for(int i=0;i<4;i++){acc[i][0]=acc[i][1]=acc[i][2]=acc[i][3]=0.f;}

    auto issue=[&](int b,int kc){
        #pragma unroll
        for(int j=0;j<2;j++){ int id=tid+j*512; int r=id>>3, c4=(id&7)<<2;
            cpa16(&Xs[b*4608 + r*36 + c4], &Ap[r*DM + kc*32 + c4]); }
        { int r=tid>>4, c4=(tid&15)<<2;
            cpa16(&Ws[b*2304 + r*72 + c4], &W[(kc*32+r)*DM + n0 + c4]); }
        cpcommit();
    };
    issue(0,kcb);
    for(int i=0;i<kcn;i++){
        if(i<kcn-1){ issue((i+1)&1, kcb+i+1); cpwait1(); } else cpwait0();
        __syncthreads();
        const float* xb = &Xs[(i&1)*4608];
        const float* wb = &Ws[(i&1)*2304];
        #pragma unroll
        for(int kk=0;kk<32;kk+=8){
            uint32_t a0=f2t(xb[(m0+gid)*36+kk+tg]);
            uint32_t a1=f2t(xb[(m0+gid+8)*36+kk+tg]);
            uint32_t a2=f2t(xb[(m0+gid)*36+kk+tg+4]);
            uint32_t a3=f2t(xb[(m0+gid+8)*36+kk+tg+4]);
            #pragma unroll
            for(int nt=0;nt<4;nt++){
                uint32_t b0=f2t(wb[(kk+tg)*72+nb+nt*8+gid]);
                uint32_t b1=f2t(wb[(kk+tg+4)*72+nb+nt*8+gid]);
                mma8(acc[nt],a0,a1,a2,a3,b0,b1);
            }
        }
        __syncthreads();
    }
    #pragma unroll
    for(int nt=0;nt<4;nt++){
        #pragma unroll
        for(int c=0;c<4;c++){
            int row=m0+gid+((c>>1)<<3);
            int col=n0+nb+nt*8+2*tg+(c&1);
            Out[row*DM + col] = acc[nt][c];
        }
    }
    // ---- last-CTA-of-group reduce (threadFenceReduction pattern) ----
    __threadfence();
    if(tid==0){
        int grp = MODE? blockIdx.x : (sel*32 + blockIdx.x);
        int* cnt = MODE? &g_cnt1[grp] : &g_cnt0[grp];
        int need = MODE? 7 : 2;
        int old = atomicAdd(cnt, 1);
        lastFlag = (old==need);
        if(old==need) *cnt = 0;          // self-reset for next graph replay
    }
    __syncthreads();
    if(!lastFlag) return;
    __threadfence();
    if(MODE){
        // reduce 8 partials + bias -> O, tile rows 0..127, cols n0..n0+63
        for(int j=0;j<4;j++){
            int idx = tid + j*512;            // 2048 float4
            int row = idx>>4;
            int col = n0 + ((idx&15)<<2);
            int base = row*DM + col;
            float4 a0=*(const float4*)&g_part[0*262144+base];
            float4 a1=*(const float4*)&g_part[1*262144+base];
            float4 a2=*(const float4*)&g_part[2*262144+base];
            float4 a3=*(const float4*)&g_part[3*262144+base];
            float4 a4=*(const float4*)&g_part[4*262144+base];
            float4 a5=*(const float4*)&g_part[5*262144+base];
            float4 a6=*(const float4*)&g_part[6*262144+base];
            float4 a7=*(const float4*)&g_part[7*262144+base];
            float4 b=*(const float4*)&Bi[col];
            float4 o;
            o.x=((a0.x+a1.x)+(a2.x+a3.x))+((a4.x+a5.x)+(a6.x+a7.x))+b.x;
            o.y=((a0.y+a1.y)+(a2.y+a3.y))+((a4.y+a5.y)+(a6.y+a7.y))+b.y;
            o.z=((a0.z+a1.z)+(a2.z+a3.z))+((a4.z+a5.z)+(a6.z+a7.z))+b.z;
            o.w=((a0.w+a1.w)+(a2.w+a3.w))+((a4.w+a5.w)+(a6.w+a7.w))+b.w;
            *(float4*)&O[base]=o;
        }
    }else{
        // reduce 3 partials + bias -> per-head scatter into g_q/g_kn/g_vn
        const float* P = g_pqkv + sel*3*262144;
        float* dst = sel==0?g_q: sel==1?g_kn:g_vn;
        for(int j=0;j<4;j++){
            int idx = tid + j*512;
            int row = idx>>4;
            int col = n0 + ((idx&15)<<2);
            int base = row*DM + col;
            float4 p0=*(const float4*)&P[base];
            float4 p1=*(const float4*)&P[262144+base];
            float4 p2=*(const float4*)&P[524288+base];
            float4 b=*(const float4*)&Bi[col];
            float4 o;
            o.x=p0.x+p1.x+p2.x+b.x; o.y=p0.y+p1.y+p2.y+b.y;
            o.z=p0.z+p1.z+p2.z+b.z; o.w=p0.w+p1.w+p2.w+b.w;
            int off = (((row>>4)<<4)|(col>>7))*2048 + (row&15)*128 + (col&127);
            *(float4*)&dst[off]=o;
        }
    }
}

// ======================= Flash attention (round-16, frozen) ===============
#define KS_STR 132
#define VS_STR 136
#define KBUF (64*KS_STR)
#define VBUF (64*VS_STR)
#define ATTN_SMEM ((3*KBUF + 3*VBUF + 16*132 + 8*192)*4)

__global__ __launch_bounds__(256) void attn_k(const float* __restrict__ kc_,
                                              const float* __restrict__ vc_)
{
    extern __shared__ float sm[];
    float* Ks   = sm;
    float* Vs   = sm + 3*KBUF;
    float* qs   = Vs + 3*VBUF;
    float* psm  = qs + 16*132;
    float* Osum = sm;
    float* Lsum = sm + 2112;
    float* msh  = sm + 2128;
    int tid=threadIdx.x, lane=tid&31, warp=tid>>5, tg=lane&3, gid=lane>>2;
    int bh=blockIdx.x;
    const float cs = 0.08838834764831843f * 1.4426950408889634f;
    #pragma unroll
    for(int j=tid;j<512;j+=256){
        float4 v=*(const float4*)&g_q[bh*2048+j*4];
        int r=j>>5, c4=(j&31)<<2;
        qs[r*132+c4+0]=tf(v.x*cs); qs[r*132+c4+1]=tf(v.y*cs);
        qs[r*132+c4+2]=tf(v.z*cs); qs[r*132+c4+3]=tf(v.w*cs);
    }
    const float* Kc = kc_ + (size_t)bh*4096*128;
    const float* Vc = vc_ + (size_t)bh*4096*128;

    auto issue=[&](int t){
        float* kd=&Ks[(t%3)*KBUF];
        float* vd=&Vs[(t%3)*VBUF];
        #pragma unroll
        for(int j=0;j<8;j++){ int id=tid+j*256; int r=id>>5, c4=(id&31)<<2;
            cpa16(&kd[r*KS_STR + c4], &Kc[(size_t)(t*64+r)*128 + c4]); }
        #pragma unroll
        for(int j=0;j<8;j++){ int id=tid+j*256; int r=id>>5, c4=(id&31)<<2;
            cpa16(&vd[r*VS_STR + c4], &Vc[(size_t)(t*64+r)*128 + c4]); }
        cpcommit();
    };
    issue(0); issue(1);
    __syncthreads();

    uint32_t aq0[16],aq1[16],aq2[16],aq3[16];
    #pragma unroll
    for(int k8=0;k8<16;k8++){
        aq0[k8]=__float_as_uint(qs[gid*132+k8*8+tg]);
        aq1[k8]=__float_as_uint(qs[(gid+8)*132+k8*8+tg]);
        aq2[k8]=__float_as_uint(qs[gid*132+k8*8+tg+4]);
        aq3[k8]=__float_as_uint(qs[(gid+8)*132+k8*8+tg+4]);
    }

    float accO[16][4];
    #pragma unroll
    for(int i=0;i<16;i++){accO[i][0]=accO[i][1]=accO[i][2]=accO[i][3]=0.f;}
    float m0=-1e30f,m1=-1e30f,l0=0.f,l1=0.f;
    float* pw = psm + warp*192;

    for(int t=0;t<64;t++){
        if(t<63) cpwait1(); else cpwait0();
        __syncthreads();
        if(t+2<64) issue(t+2);
        const float* Kb=&Ks[(t%3)*KBUF];
        const float* Vb=&Vs[(t%3)*VBUF];
        float s[4]={0.f,0.f,0.f,0.f};
        #pragma unroll
        for(int k8=0;k8<16;k8++){
            uint32_t b0=f2t(Kb[(warp*8+gid)*KS_STR+k8*8+tg]);
            uint32_t b1=f2t(Kb[(warp*8+gid)*KS_STR+k8*8+tg+4]);
            mma8(s,aq0[k8],aq1[k8],aq2[k8],aq3[k8],b0,b1);
        }
        float x0=fmaxf(s[0],s[1]), x1=fmaxf(s[2],s[3]);
        x0=fmaxf(x0,__shfl_xor_sync(~0u,x0,1)); x0=fmaxf(x0,__shfl_xor_sync(~0u,x0,2));
        x1=fmaxf(x1,__shfl_xor_sync(~0u,x1,1)); x1=fmaxf(x1,__shfl_xor_sync(~0u,x1,2));
        bool upd = __any_sync(~0u,(x0>m0)||(x1>m1));
        float nm0=fmaxf(m0,x0), nm1=fmaxf(m1,x1);
        float f0=1.f,f1=1.f;
        if(upd){
            f0=ex2(m0-nm0); f1=ex2(m1-nm1);
            m0=nm0; m1=nm1;
            #pragma unroll
            for(int i=0;i<16;i++){accO[i][0]*=f0;accO[i][1]*=f0;accO[i][2]*=f1;accO[i][3]*=f1;}
        }
        float p0=ex2(s[0]-nm0), p1=ex2(s[1]-nm0);
        float p2=ex2(s[2]-nm1), p3=ex2(s[3]-nm1);
        float su0=p0+p1, su1=p2+p3;
        su0+=__shfl_xor_sync(~0u,su0,1); su0+=__shfl_xor_sync(~0u,su0,2);
        su1+=__shfl_xor_sync(~0u,su1,1); su1+=__shfl_xor_sync(~0u,su1,2);
        l0=l0*f0+su0; l1=l1*f1+su1;
        pw[gid*12+2*tg]=p0;     pw[gid*12+2*tg+1]=p1;
        pw[(gid+8)*12+2*tg]=p2; pw[(gid+8)*12+2*tg+1]=p3;
        __syncwarp();
        uint32_t h0=f2t(pw[gid*12+tg]);
        uint32_t h1=f2t(pw[(gid+8)*12+tg]);
        uint32_t h2=f2t(pw[gid*12+tg+4]);
        uint32_t h3=f2t(pw[(gid+8)*12+tg+4]);
        #pragma unroll
        for(int nt=0;nt<16;nt++){
            uint32_t b0=f2t(Vb[(warp*8+tg)*VS_STR+nt*8+gid]);
            uint32_t b1=f2t(Vb[(warp*8+tg+4)*VS_STR+nt*8+gid]);
            mma8(accO[nt],h0,h1,h2,h3,b0,b1);
        }
        __syncwarp();
    }
    __syncthreads();

    if(warp<2){
        const float* Kp = g_kn + bh*2048 + warp*8*128;
        const float* Vp = g_vn + bh*2048 + warp*8*128;
        float s[4]={0.f,0.f,0.f,0.f};
        #pragma unroll
        for(int k8=0;k8<16;k8++){
            uint32_t b0=f2t(Kp[gid*128+k8*8+tg]);
            uint32_t b1=f2t(Kp[gid*128+k8*8+tg+4]);
            mma8(s,aq0[k8],aq1[k8],aq2[k8],aq3[k8],b0,b1);
        }
        #pragma unroll
        for(int c=0;c<4;c++){
            int col16=warp*8+2*tg+(c&1), row=gid+((c>>1)<<3);
            if(col16>row) s[c]=-1e30f;
        }
        float x0=fmaxf(s[0],s[1]), x1=fmaxf(s[2],s[3]);
        x0=fmaxf(x0,__shfl_xor_sync(~0u,x0,1)); x0=fmaxf(x0,__shfl_xor_sync(~0u,x0,2));
        x1=fmaxf(x1,__shfl_xor_sync(~0u,x1,1)); x1=fmaxf(x1,__shfl_xor_sync(~0u,x1,2));
        float nm0=fmaxf(m0,x0), nm1=fmaxf(m1,x1);
        float f0=ex2(m0-nm0), f1=ex2(m1-nm1);
        m0=nm0; m1=nm1;
        float p0=ex2(s[0]-nm0), p1=ex2(s[1]-nm0);
        float p2=ex2(s[2]-nm1), p3=ex2(s[3]-nm1);
        float su0=p0+p1, su1=p2+p3;
        su0+=__shfl_xor_sync(~0u,su0,1); su0+=__shfl_xor_sync(~0u,su0,2);
        su1+=__shfl_xor_sync(~0u,su1,1); su1+=__shfl_xor_sync(~0u,su1,2);
        l0=l0*f0+su0; l1=l1*f1+su1;
        #pragma unroll
        for(int i=0;i<16;i++){accO[i][0]*=f0;accO[i][1]*=f0;accO[i][2]*=f1;accO[i][3]*=f1;}
        pw[gid*12+2*tg]=p0;     pw[gid*12+2*tg+1]=p1;
        pw[(gid+8)*12+2*tg]=p2; pw[(gid+8)*12+2*tg+1]=p3;
        __syncwarp();
        uint32_t h0=f2t(pw[gid*12+tg]);
        uint32_t h1=f2t(pw[(gid+8)*12+tg]);
        uint32_t h2=f2t(pw[gid*12+tg+4]);
        uint32_t h3=f2t(pw[(gid+8)*12+tg+4]);
        #pragma unroll
        for(int nt=0;nt<16;nt++){
            uint32_t b0=f2t(Vp[tg*128+nt*8+gid]);
            uint32_t b1=f2t(Vp[(tg+4)*128+nt*8+gid]);
            mma8(accO[nt],h0,h1,h2,h3,b0,b1);
        }
    }
    __syncthreads();

    for(int j=tid;j<2144;j+=256) sm[j]=0.f;
    __syncthreads();
    if(tg==0){ msh[warp*16+gid]=m0; msh[warp*16+gid+8]=m1; }
    __syncthreads();
    float M0=-1e30f,M1=-1e30f;
    #pragma unroll
    for(int w=0;w<8;w++){ M0=fmaxf(M0,msh[w*16+gid]); M1=fmaxf(M1,msh[w*16+gid+8]); }
    float sc0=ex2(m0-M0), sc1=ex2(m1-M1);
    if(tg==0){ atomicAdd(&Lsum[gid],l0*sc0); atomicAdd(&Lsum[gid+8],l1*sc1); }
    #pragma unroll
    for(int nt=0;nt<16;nt++){
        atomicAdd(&Osum[gid*132+nt*8+2*tg],       accO[nt][0]*sc0);
        atomicAdd(&Osum[gid*132+nt*8+2*tg+1],     accO[nt][1]*sc0);
        atomicAdd(&Osum[(gid+8)*132+nt*8+2*tg],   accO[nt][2]*sc1);
        atomicAdd(&Osum[(gid+8)*132+nt*8+2*tg+1], accO[nt][3]*sc1);
    }
    __syncthreads();
    int b=bh>>4, h=bh&15;
    for(int j=tid;j<2048;j+=256){
        int s_=j>>7, d=j&127;
        g_ao[(b*16+s_)*2048 + h*128 + d] = Osum[s_*132+d]/Lsum[s_];
    }
}

extern "C" void kernel_launch(void* const* d_in, const int* in_sizes, int n_in,
                              void* d_out, int out_size)
{
    const float* x =(const float*)d_in[0];
    const float* kc=(const float*)d_in[1];
    const float* vc=(const float*)d_in[2];
    const float* Wq=(const float*)d_in[3]; const float* bq=(const float*)d_in[4];
    const float* Wk=(const float*)d_in[5]; const float* bk=(const float*)d_in[6];
    const float* Wv=(const float*)d_in[7]; const float* bv=(const float*)d_in[8];
    const float* Wo=(const float*)d_in[9]; const float* bo=(const float*)d_in[10];
    cudaFuncSetAttribute(gemm_k<0>, cudaFuncAttributeMaxDynamicSharedMemorySize, GEMM_SMEM);
    cudaFuncSetAttribute(gemm_k<1>, cudaFuncAttributeMaxDynamicSharedMemorySize, GEMM_SMEM);
    cudaFuncSetAttribute(attn_k,    cudaFuncAttributeMaxDynamicSharedMemorySize, ATTN_SMEM);
    gemm_k<0><<<dim3(32,3,3),512,GEMM_SMEM>>>(x,Wq,Wk,Wv,bq,bk,bv,nullptr);
    attn_k<<<128,256,ATTN_SMEM>>>(kc,vc);
    gemm_k<1><<<dim3(32,8),512,GEMM_SMEM>>>(nullptr,Wo,Wo,Wo,bo,bo,bo,(float*)d_out);
}